// round 9
// baseline (speedup 1.0000x reference)
#include <cuda_runtime.h>

#define BDIM  256
#define CHUNK 4096
#define E     16          // outputs per thread (CHUNK/BDIM)
#define NLEN  131072
#define GT    33          // composed tap count

typedef unsigned long long u64;

__device__ __forceinline__ u64 ffma2(u64 a, u64 b, u64 c) {
    u64 d;
    asm("fma.rn.f32x2 %0, %1, %2, %3;" : "=l"(d) : "l"(a), "l"(b), "l"(c));
    return d;
}
__device__ __forceinline__ u64 pack2(float lo, float hi) {
    u64 r;
    asm("mov.b64 %0, {%1, %2};" : "=l"(r) : "f"(lo), "f"(hi));
    return r;
}
__device__ __forceinline__ float2 unpk(u64 v) {
    float2 r;
    asm("mov.b64 {%0, %1}, %2;" : "=f"(r.x), "=f"(r.y) : "l"(v));
    return r;
}

__global__ __launch_bounds__(BDIM, 2)
void fir2c_kernel(const float* __restrict__ x,
                  const float* __restrict__ kern,
                  float* __restrict__ out) {
    __shared__ __align__(16) float xs[CHUNK + 32];   // x[chunkStart-32 .. chunkStart+CHUNK)
    __shared__ __align__(8)  float g2[2 * GT];       // composed taps, duplicated for LDS.64
    __shared__ float hsm[16];

    const int tid = threadIdx.x;
    const int row = blockIdx.y;
    const int chunkStart = blockIdx.x * CHUNK;
    const float* xrow = x + (size_t)row * NLEN;
    float* orow = out + (size_t)row * NLEN;

    if (tid < 16) hsm[tid] = kern[tid];

    // ---- cooperative vectorized load of x tile + 32-left halo ----
    {
        const int gbase = chunkStart - 32;
        for (int i = tid; i < (CHUNK + 32) / 4; i += BDIM) {
            int g = gbase + 4 * i;                 // whole vec in/out of range
            float4 v = make_float4(0.f, 0.f, 0.f, 0.f);
            if (g >= 0) v = *(const float4*)(xrow + g);
            ((float4*)xs)[i] = v;
        }
    }
    __syncthreads();   // hsm + xs visible

    // ---- compose g = (delta + hr) * (delta + h): 33 taps, duplicated ----
    if (tid < GT) {
        float acc = (tid == 0) ? 1.f : 0.f;
        if (tid >= 1 && tid <= 16) acc += hsm[tid - 1] + hsm[16 - tid];
        int mlo = (tid - 16 > 1) ? tid - 16 : 1;
        int mhi = (tid - 1 < 16) ? tid - 1 : 16;
        for (int m = mlo; m <= mhi; m++)
            acc += hsm[m - 1] * hsm[16 - (tid - m)];
        g2[2 * tid]     = acc;
        g2[2 * tid + 1] = acc;
    }
    __syncthreads();

    const int base = tid * E;                       // local output base
    const bool fixup = (chunkStart == 0) && (tid < 2);

    if (!fixup) {
        // window w[j] = xs[base + j] = x[chunkStart + base - 32 + j], j in [0,48)
        float w[48];
        #pragma unroll
        for (int q = 0; q < 12; q++)
            ((float4*)w)[q] = *(const float4*)&xs[base + 4 * q];

        // even pairs alias the LDS.128 quads (register-aligned -> free);
        // odd pairs need explicit packs (ALU pipe, has headroom)
        u64 wa[24], wb[23];
        #pragma unroll
        for (int i = 0; i < 24; i++) wa[i] = pack2(w[2 * i], w[2 * i + 1]);
        #pragma unroll
        for (int i = 0; i < 23; i++) wb[i] = pack2(w[2 * i + 1], w[2 * i + 2]);

        u64 acc[E / 2];
        #pragma unroll
        for (int p = 0; p < E / 2; p++) acc[p] = 0ull;

        // y[base+o] = sum_d g[d] * w[o + 32 - d]
        #pragma unroll
        for (int d = 0; d < GT; d++) {
            u64 gg = *(const u64*)(g2 + 2 * d);     // LDS.64 broadcast of (g,g)
            #pragma unroll
            for (int p = 0; p < E / 2; p++) {
                const int j = 2 * p + 32 - d;
                u64 wv = (j & 1) ? wb[j >> 1] : wa[j >> 1];
                acc[p] = ffma2(gg, wv, acc[p]);
            }
        }

        #pragma unroll
        for (int p = 0; p < E / 2; p += 2) {
            float2 a = unpk(acc[p]);
            float2 b = unpk(acc[p + 1]);
            *(float4*)(orow + chunkStart + base + 2 * p) =
                make_float4(a.x, a.y, b.x, b.y);
        }
    } else {
        // chunkStart == 0: outputs [0,32) where the intermediate mask matters.
        if (tid == 0) {
            #pragma unroll
            for (int q = 0; q < 4; q++)
                *(float4*)(orow + 4 * q) = make_float4(0.f, 0.f, 0.f, 0.f);
        } else {
            // exact two-stage for y[16..31]; needs x[0..31] = xs[32..63]
            float h[16];
            #pragma unroll
            for (int j = 0; j < 16; j++) h[j] = hsm[j];
            float xv[32];
            #pragma unroll
            for (int t = 0; t < 32; t++) xv[t] = xs[32 + t];

            float u[16];                            // u[m] = v[16+m]
            #pragma unroll
            for (int m = 0; m < 16; m++) {
                float a = xv[16 + m];
                #pragma unroll
                for (int j = 0; j < 16; j++)
                    a = fmaf(h[j], xv[15 + m - j], a);
                u[m] = a;
            }
            #pragma unroll
            for (int o = 0; o < 16; o++) {
                float a = u[o];                     // v[16+o]
                for (int j = 0; j < o; j++)         // only v>=16 terms survive mask
                    a = fmaf(h[15 - j], u[o - j - 1], a);
                orow[16 + o] = a;
            }
        }
    }
}

extern "C" void kernel_launch(void* const* d_in, const int* in_sizes, int n_in,
                              void* d_out, int out_size) {
    const float* x    = (const float*)d_in[0];   // (256, 131072) f32
    const float* kern = (const float*)d_in[1];   // (1, 16) f32
    float* out        = (float*)d_out;

    dim3 grid(NLEN / CHUNK, 256, 1);             // 32 x 256 = 8192 CTAs
    fir2c_kernel<<<grid, BDIM>>>(x, kern, out);
}

// round 10
// speedup vs baseline: 1.2017x; 1.2017x over previous
#include <cuda_runtime.h>

#define BDIM  256
#define CHUNK 2048
#define E     8           // outputs per thread (CHUNK/BDIM)
#define NLEN  131072
#define GT    33          // composed tap count

typedef unsigned long long u64;

__device__ __forceinline__ u64 ffma2(u64 a, u64 b, u64 c) {
    u64 d;
    asm("fma.rn.f32x2 %0, %1, %2, %3;" : "=l"(d) : "l"(a), "l"(b), "l"(c));
    return d;
}
__device__ __forceinline__ u64 pack2(float lo, float hi) {
    u64 r;
    asm("mov.b64 %0, {%1, %2};" : "=l"(r) : "f"(lo), "f"(hi));
    return r;
}
__device__ __forceinline__ float2 unpk(u64 v) {
    float2 r;
    asm("mov.b64 {%0, %1}, %2;" : "=f"(r.x), "=f"(r.y) : "l"(v));
    return r;
}

__global__ __launch_bounds__(BDIM, 2)
void fir2c_kernel(const float* __restrict__ x,
                  const float* __restrict__ kern,
                  float* __restrict__ out) {
    __shared__ __align__(16) float xs[CHUNK + 32];   // x[chunkStart-32 .. chunkStart+CHUNK)
    __shared__ __align__(8)  float g2[2 * GT];       // composed taps, duplicated for LDS.64
    __shared__ float hsm[16];

    const int tid = threadIdx.x;
    const int row = blockIdx.y;
    const int chunkStart = blockIdx.x * CHUNK;
    const float* xrow = x + (size_t)row * NLEN;
    float* orow = out + (size_t)row * NLEN;

    if (tid < 16) hsm[tid] = kern[tid];

    // ---- cooperative vectorized load of x tile + 32-left halo ----
    {
        const int gbase = chunkStart - 32;
        #pragma unroll
        for (int i = tid; i < (CHUNK + 32) / 4; i += BDIM) {
            int g = gbase + 4 * i;                 // whole vec in/out of range
            float4 v = make_float4(0.f, 0.f, 0.f, 0.f);
            if (g >= 0) v = *(const float4*)(xrow + g);
            ((float4*)xs)[i] = v;
        }
    }
    __syncthreads();   // hsm + xs visible

    // ---- compose g = (delta + hr) * (delta + h): 33 taps, duplicated ----
    if (tid < GT) {
        float acc = (tid == 0) ? 1.f : 0.f;
        if (tid >= 1 && tid <= 16) acc += hsm[tid - 1] + hsm[16 - tid];
        int mlo = (tid - 16 > 1) ? tid - 16 : 1;
        int mhi = (tid - 1 < 16) ? tid - 1 : 16;
        for (int m = mlo; m <= mhi; m++)
            acc += hsm[m - 1] * hsm[16 - (tid - m)];
        g2[2 * tid]     = acc;
        g2[2 * tid + 1] = acc;
    }
    __syncthreads();

    const int base = tid * E;                       // local output base
    const bool fixup = (chunkStart == 0) && (tid < 4);

    if (!fixup) {
        // window w[j] = xs[base + j] = x[chunkStart + base - 32 + j], j in [0,40)
        float w[40];
        #pragma unroll
        for (int q = 0; q < 10; q++)
            ((float4*)w)[q] = *(const float4*)&xs[base + 4 * q];

        u64 acc[E / 2];
        #pragma unroll
        for (int p = 0; p < E / 2; p++) acc[p] = 0ull;

        // y[base+o] = sum_d g[d] * w[o + 32 - d]
        // pairs packed on the fly: even-j aligned (free reg pairs),
        // odd-j CSE'd across (p,d) by ptxas (19 distinct crossing pairs)
        #pragma unroll
        for (int d = 0; d < GT; d++) {
            u64 gg = *(const u64*)(g2 + 2 * d);     // LDS.64 broadcast of (g,g)
            #pragma unroll
            for (int p = 0; p < E / 2; p++) {
                const int j = 2 * p + 32 - d;       // 0..39
                acc[p] = ffma2(gg, pack2(w[j], w[j + 1]), acc[p]);
            }
        }

        #pragma unroll
        for (int p = 0; p < E / 2; p += 2) {
            float2 a = unpk(acc[p]);
            float2 b = unpk(acc[p + 1]);
            *(float4*)(orow + chunkStart + base + 2 * p) =
                make_float4(a.x, a.y, b.x, b.y);
        }
    } else {
        // chunkStart == 0: outputs [0,32); intermediate mask matters here.
        if (tid == 0 || tid == 1) {
            // y[0..15] = 0
            #pragma unroll
            for (int q = 0; q < 2; q++)
                *(float4*)(orow + tid * E + 4 * q) = make_float4(0.f, 0.f, 0.f, 0.f);
        } else if (tid == 2) {
            // exact two-stage for y[16..31]; needs x[0..31] = xs[32..63]
            float h[16];
            #pragma unroll
            for (int j = 0; j < 16; j++) h[j] = hsm[j];
            float xv[32];
            #pragma unroll
            for (int t = 0; t < 32; t++) xv[t] = xs[32 + t];

            float u[16];                            // u[m] = v[16+m]
            #pragma unroll
            for (int m = 0; m < 16; m++) {
                float a = xv[16 + m];
                #pragma unroll
                for (int j = 0; j < 16; j++)
                    a = fmaf(h[j], xv[15 + m - j], a);
                u[m] = a;
            }
            #pragma unroll
            for (int o = 0; o < 16; o++) {
                float a = u[o];                     // v[16+o]
                for (int j = 0; j < o; j++)         // only v>=16 terms survive mask
                    a = fmaf(h[15 - j], u[o - j - 1], a);
                orow[16 + o] = a;
            }
        }
        // tid == 3: outputs 24..31 handled by tid 2
    }
}

extern "C" void kernel_launch(void* const* d_in, const int* in_sizes, int n_in,
                              void* d_out, int out_size) {
    const float* x    = (const float*)d_in[0];   // (256, 131072) f32
    const float* kern = (const float*)d_in[1];   // (1, 16) f32
    float* out        = (float*)d_out;

    dim3 grid(NLEN / CHUNK, 256, 1);             // 64 x 256 = 16384 CTAs
    fir2c_kernel<<<grid, BDIM>>>(x, kern, out);
}

// round 12
// speedup vs baseline: 1.2790x; 1.0643x over previous
#include <cuda_runtime.h>

#define BDIM  256
#define CHUNK 4096
#define E     16          // outputs per thread (CHUNK/BDIM)
#define NLEN  131072
#define GT    33          // composed tap count

// padded smem layout: 4 floats of pad per 16 floats -> per-lane window stride
// 80B, (i*80) mod 128 covers all 8 bank quads => conflict-free LDS.128
#define PHYS(idx) ((idx) + (((idx) >> 4) << 2))
#define XS_LOG   (CHUNK + 32)                    // 4128 logical floats
#define XS_PHYS  (XS_LOG + (XS_LOG / 16) * 4)    // 5160 floats = 20640 B

typedef unsigned long long u64;

__device__ __forceinline__ u64 ffma2(u64 a, u64 b, u64 c) {
    u64 d;
    asm("fma.rn.f32x2 %0, %1, %2, %3;" : "=l"(d) : "l"(a), "l"(b), "l"(c));
    return d;
}
__device__ __forceinline__ u64 pack2(float lo, float hi) {
    u64 r;
    asm("mov.b64 %0, {%1, %2};" : "=l"(r) : "f"(lo), "f"(hi));
    return r;
}
__device__ __forceinline__ float2 unpk(u64 v) {
    float2 r;
    asm("mov.b64 {%0, %1}, %2;" : "=f"(r.x), "=f"(r.y) : "l"(v));
    return r;
}

__global__ __launch_bounds__(BDIM, 2)
void fir2c_kernel(const float* __restrict__ x,
                  const float* __restrict__ kern,
                  float* __restrict__ out) {
    __shared__ __align__(16) float xs[XS_PHYS];      // padded x tile
    __shared__ __align__(8)  float g2[2 * GT];       // composed taps, duplicated for LDS.64
    __shared__ float hsm[16];

    const int tid = threadIdx.x;
    const int row = blockIdx.y;
    const int chunkStart = blockIdx.x * CHUNK;
    const float* xrow = x + (size_t)row * NLEN;
    float* orow = out + (size_t)row * NLEN;

    if (tid < 16) hsm[tid] = kern[tid];

    // ---- cooperative vectorized load of x tile + 32-left halo (padded STS) ----
    {
        const int gbase = chunkStart - 32;
        #pragma unroll
        for (int i = tid; i < XS_LOG / 4; i += BDIM) {
            int idx = 4 * i;                       // logical float index, quad-aligned
            int g = gbase + idx;                   // whole quad in/out of range
            float4 v = make_float4(0.f, 0.f, 0.f, 0.f);
            if (g >= 0) v = *(const float4*)(xrow + g);
            *(float4*)&xs[PHYS(idx)] = v;
        }
    }
    __syncthreads();   // hsm + xs visible

    // ---- compose g = (delta + hr) * (delta + h): 33 taps, duplicated ----
    if (tid < GT) {
        float acc = (tid == 0) ? 1.f : 0.f;
        if (tid >= 1 && tid <= 16) acc += hsm[tid - 1] + hsm[16 - tid];
        int mlo = (tid - 16 > 1) ? tid - 16 : 1;
        int mhi = (tid - 1 < 16) ? tid - 1 : 16;
        for (int m = mlo; m <= mhi; m++)
            acc += hsm[m - 1] * hsm[16 - (tid - m)];
        g2[2 * tid]     = acc;
        g2[2 * tid + 1] = acc;
    }
    __syncthreads();

    const int base = tid * E;                       // local output base
    const bool fixup = (chunkStart == 0) && (tid < 2);

    if (!fixup) {
        // window w[j] = xs_log[base + j] = x[chunkStart + base - 32 + j], j in [0,48)
        float w[48];
        #pragma unroll
        for (int q = 0; q < 12; q++) {
            const int idx = base + 4 * q;          // quad never straddles a pad boundary
            ((float4*)w)[q] = *(const float4*)&xs[PHYS(idx)];
        }

        u64 acc[E / 2];
        #pragma unroll
        for (int p = 0; p < E / 2; p++) acc[p] = 0ull;

        // y[base+o] = sum_d g[d] * w[o + 32 - d]
        // pairs packed on the fly: even-j pairs are aligned halves of the
        // LDS.128 quads (free); odd-j pairs CSE across consecutive odd d
        #pragma unroll
        for (int d = 0; d < GT; d++) {
            u64 gg = *(const u64*)(g2 + 2 * d);     // LDS.64 broadcast of (g,g)
            #pragma unroll
            for (int p = 0; p < E / 2; p++) {
                const int j = 2 * p + 32 - d;       // 0..47
                acc[p] = ffma2(gg, pack2(w[j], w[j + 1]), acc[p]);
            }
        }

        #pragma unroll
        for (int p = 0; p < E / 2; p += 2) {
            float2 a = unpk(acc[p]);
            float2 b = unpk(acc[p + 1]);
            *(float4*)(orow + chunkStart + base + 2 * p) =
                make_float4(a.x, a.y, b.x, b.y);
        }
    } else {
        // chunkStart == 0: outputs [0,32); the intermediate mask matters here.
        if (tid == 0) {
            // y[0..15] = 0
            #pragma unroll
            for (int q = 0; q < 4; q++)
                *(float4*)(orow + 4 * q) = make_float4(0.f, 0.f, 0.f, 0.f);
        } else {
            // exact two-stage for y[16..31]; needs x[0..31] = xs_log[32..63]
            float h[16];
            #pragma unroll
            for (int j = 0; j < 16; j++) h[j] = hsm[j];
            float xv[32];
            #pragma unroll
            for (int t = 0; t < 32; t++) {
                const int idx = 32 + t;
                xv[t] = xs[PHYS(idx)];
            }

            float u[16];                            // u[m] = v[16+m]
            #pragma unroll
            for (int m = 0; m < 16; m++) {
                float a = xv[16 + m];
                #pragma unroll
                for (int j = 0; j < 16; j++)
                    a = fmaf(h[j], xv[15 + m - j], a);
                u[m] = a;
            }
            #pragma unroll
            for (int o = 0; o < 16; o++) {
                float a = u[o];                     // v[16+o]
                for (int j = 0; j < o; j++)         // only v>=16 terms survive mask
                    a = fmaf(h[15 - j], u[o - j - 1], a);
                orow[16 + o] = a;
            }
        }
    }
}

extern "C" void kernel_launch(void* const* d_in, const int* in_sizes, int n_in,
                              void* d_out, int out_size) {
    const float* x    = (const float*)d_in[0];   // (256, 131072) f32
    const float* kern = (const float*)d_in[1];   // (1, 16) f32
    float* out        = (float*)d_out;

    dim3 grid(NLEN / CHUNK, 256, 1);             // 32 x 256 = 8192 CTAs
    fir2c_kernel<<<grid, BDIM>>>(x, kern, out);
}